// round 16
// baseline (speedup 1.0000x reference)
#include <cuda_runtime.h>

#define TT     512
#define CHUNK  16
#define NPAIR  8
#define NCHUNK 32
#define NBH    64
#define ROWP   68

__device__ float g_Wsnap[(size_t)NBH * NCHUNK * 4096];
__device__ float g_bsnap[(size_t)NBH * NCHUNK * 64];
__device__ int   g_prog[NBH];

#define CPA16(saddr, gptr) \
    asm volatile("cp.async.cg.shared.global [%0], [%1], 16;" :: "r"(saddr), "l"(gptr))
#define CPCOMMIT() asm volatile("cp.async.commit_group;")
#define CPWAIT0()  asm volatile("cp.async.wait_group 0;")

// chunk-role dyn smem layout (floats)
#define OFF_XQ  4096                  // 4 buffers x 1088
#define OFF_XK  (OFF_XQ + 4352)
#define OFF_GZ  (OFF_XK + 4352)
#define OFF_BB  (OFF_GZ + 1088)
#define OFF_ETA (OFF_BB + 64)         // 4 x 16
#define SMF     (OFF_ETA + 64)        // 14016 floats = 56 KB

__global__ void reset_kernel() {
    if (threadIdx.x < NBH) g_prog[threadIdx.x] = 0;
}

// ========== scan role (R13-proven): 128 threads, 4-warp d-split =============
__device__ __forceinline__
void scan_role(float* sm, int bh,
               const float* __restrict__ XK, const float* __restrict__ XV,
               const float* __restrict__ W1, const float* __restrict__ b1,
               const float* __restrict__ gam, const float* __restrict__ bet)
{
    float* const xs = sm;            // 64
    float* const pz = sm + 64;       // 4 x 64
    float* const gs = sm + 320;      // 64

    const int tid  = threadIdx.x;
    const int lane = tid & 31;
    const int w    = tid >> 5;
    const int h    = bh & 15;

    float Wa[16], Wb[16];
    {
        const float* Wg = W1 + (size_t)h * 4096;
        #pragma unroll
        for (int i = 0; i < 16; i++) {
            const int d = w*16 + i;
            Wa[i] = Wg[d*64 + lane];
            Wb[i] = Wg[d*64 + lane + 32];
        }
    }
    float bav = b1[h*64 + lane], bbv = b1[h*64 + lane + 32];
    const float ga  = gam[h*64 + lane], gb  = gam[h*64 + lane + 32];
    const float bea = bet[h*64 + lane], beb = bet[h*64 + lane + 32];

    const size_t base = (size_t)bh * (TT * 1024) + 960;   // row 15 of each step
    const float* xkg = XK + base;
    const float* xvg = XV + base;

    float kc = (tid < 64) ? xkg[tid] : 0.f;
    float va = 0.f, vb = 0.f;
    if (w == 0) { va = xvg[lane]; vb = xvg[lane + 32]; }

    for (int t = 0; t < TT; t++) {
        // snapshot W,b at chunk boundary (pre-update)
        if ((t & (CHUNK-1)) == 0) {
            const int c = t >> 4;
            float* ws = g_Wsnap + ((size_t)bh * NCHUNK + c) * 4096;
            #pragma unroll
            for (int i = 0; i < 16; i++) {
                const int d = w*16 + i;
                ws[d*64 + lane]      = Wa[i];
                ws[d*64 + lane + 32] = Wb[i];
            }
            if (w == 0) {
                float* bs = g_bsnap + ((size_t)bh * NCHUNK + c) * 64;
                bs[lane] = bav; bs[lane + 32] = bbv;
            }
        }

        // prefetch next step row-15
        float kn = 0.f, nva = 0.f, nvb = 0.f;
        if (t + 1 < TT) {
            const size_t o = (size_t)(t+1) * 1024;
            if (tid < 64) kn = xkg[o + tid];
            if (w == 0) { nva = xvg[o + lane]; nvb = xvg[o + lane + 32]; }
        }

        if (tid < 64) xs[tid] = kc;
        __syncthreads();                                    // B1

        // publish snapshot (writes complete at B1) -> release flag
        if ((t & (CHUNK-1)) == 0 && tid == 0) {
            __threadfence();
            atomicExch(&g_prog[bh], (t >> 4) + 1);
        }

        // el (redundant in every warp)
        const float xa = xs[lane], xb = xs[lane + 32];
        float ss = xa*xa + xb*xb;
        #pragma unroll
        for (int m = 16; m >= 1; m >>= 1) ss += __shfl_xor_sync(~0u, ss, m);
        const float el = 0.01f / (1.0f + fmaxf(sqrtf(ss), 1e-6f));

        // partial matvec over this warp's 16 d-rows
        float x16[16];
        float za = 0.f, zb = 0.f;
        #pragma unroll
        for (int i = 0; i < 16; i++) {
            x16[i] = xs[w*16 + i];
            za = fmaf(x16[i], Wa[i], za);
            zb = fmaf(x16[i], Wb[i], zb);
        }
        pz[w*64 + lane] = za; pz[w*64 + lane + 32] = zb;
        __syncthreads();                                    // B2

        if (w == 0) {
            const float zA = bav + ((pz[lane] + pz[64+lane]) + (pz[128+lane] + pz[192+lane]));
            const float zB = bbv + ((pz[lane+32] + pz[64+lane+32]) + (pz[128+lane+32] + pz[192+lane+32]));
            float s1 = zA + zB;
            float s2 = zA*zA + zB*zB;
            #pragma unroll
            for (int m = 16; m >= 1; m >>= 1) {
                s1 += __shfl_xor_sync(~0u, s1, m);
                s2 += __shfl_xor_sync(~0u, s2, m);
            }
            const float mu  = s1 * 0.015625f;
            const float var = fmaf(-mu, mu, s2 * 0.015625f);
            const float r   = rsqrtf(var + 1e-6f);
            const float gza = 2.0f * (fmaf(ga, (zA-mu)*r, bea) - va + xa);
            const float gzb = 2.0f * (fmaf(gb, (zB-mu)*r, beb) - vb + xb);
            gs[lane] = gza; gs[lane + 32] = gzb;
            bav = fmaf(-el, gza, bav);
            bbv = fmaf(-el, gzb, bbv);
        }
        __syncthreads();                                    // B3

        const float ea = el * gs[lane], eb = el * gs[lane + 32];
        #pragma unroll
        for (int i = 0; i < 16; i++) {
            Wa[i] = fmaf(-ea, x16[i], Wa[i]);
            Wb[i] = fmaf(-eb, x16[i], Wb[i]);
        }
        __syncthreads();                                    // B4

        kc = kn; va = nva; vb = nvb;
    }
    if (tid == 0) { __threadfence(); atomicExch(&g_prog[bh], NCHUNK + 1); }
}

// ====== chunk role: 128 threads, 8 features/thread, paired steps ============
__device__ __forceinline__
void chunk_role(float* sm, int c, int bh,
                const float* __restrict__ XQ, const float* __restrict__ XK,
                const float* __restrict__ XV, const float* __restrict__ gam,
                const float* __restrict__ bet, float* __restrict__ out)
{
    float* const W  = sm;
    float* const GZ = sm + OFF_GZ;
    float* const BB = sm + OFF_BB;

    const int tid = threadIdx.x;     // 0..127
    const int h   = bh & 15;
    const int k   = tid >> 3;        // token 0..15
    const int q8  = tid & 7;
    const int f0  = q8 << 3;         // 8 features per thread
    const int sl  = k*ROWP + f0;

    if (tid == 0) {
        volatile int* f = &g_prog[bh];
        while (*f < c + 1) __nanosleep(256);
    }
    __syncthreads();
    __threadfence();

    const size_t base = (size_t)bh * (TT * 1024) + (size_t)c * (CHUNK * 1024);
    const float* xqg = XQ + base;
    const float* xkg = XK + base;
    const float* xvg = XV + base;
    float*       og  = out + base;

    {
        const float* Ws = g_Wsnap + ((size_t)bh * NCHUNK + c) * 4096;
        #pragma unroll
        for (int i = 0; i < 8; i++)
            *(float4*)&W[i*512 + tid*4] = *(const float4*)&Ws[i*512 + tid*4];
        if (tid < 16) {
            const float* bs = g_bsnap + ((size_t)bh * NCHUNK + c) * 64;
            *(float4*)&BB[tid*4] = *(const float4*)&bs[tid*4];
        }
    }
    const float4 g40  = *(const float4*)&gam[h*64 + f0];
    const float4 g41  = *(const float4*)&gam[h*64 + f0 + 4];
    const float4 be40 = *(const float4*)&bet[h*64 + f0];
    const float4 be41 = *(const float4*)&bet[h*64 + f0 + 4];

    #pragma unroll
    for (int s = 0; s < 2; s++) {
        const float4 tq0 = *(const float4*)&xqg[s*1024 + tid*8];
        const float4 tq1 = *(const float4*)&xqg[s*1024 + tid*8 + 4];
        const float4 tk0 = *(const float4*)&xkg[s*1024 + tid*8];
        const float4 tk1 = *(const float4*)&xkg[s*1024 + tid*8 + 4];
        *(float4*)&sm[OFF_XQ + s*1088 + sl]     = tq0;
        *(float4*)&sm[OFF_XQ + s*1088 + sl + 4] = tq1;
        *(float4*)&sm[OFF_XK + s*1088 + sl]     = tk0;
        *(float4*)&sm[OFF_XK + s*1088 + sl + 4] = tk1;
        float ss = tk0.x*tk0.x + tk0.y*tk0.y + tk0.z*tk0.z + tk0.w*tk0.w
                 + tk1.x*tk1.x + tk1.y*tk1.y + tk1.z*tk1.z + tk1.w*tk1.w;
        #pragma unroll
        for (int m = 4; m >= 1; m >>= 1) ss += __shfl_xor_sync(~0u, ss, m, 8);
        if (q8 == 0) sm[OFF_ETA + s*16 + k] = 0.01f / (1.0f + fmaxf(sqrtf(ss), 1e-6f));
    }
    __syncthreads();

    for (int p = 0; p < NPAIR; p++) {
        const int bA = (p & 1) * 2, bB = bA + 1;
        const int nA = ((p + 1) & 1) * 2, nB = nA + 1;
        const float* xqA  = sm + OFF_XQ + bA*1088;
        const float* xkA_ = sm + OFF_XK + bA*1088;
        const float* xqB  = sm + OFF_XQ + bB*1088;
        const float* xkB  = sm + OFF_XK + bB*1088;

        if (p + 1 < NPAIR) {
            const size_t o1 = (size_t)(2*p+2)*1024 + tid*8;
            const size_t o2 = o1 + 1024;
            CPA16((unsigned)__cvta_generic_to_shared(&sm[OFF_XQ + nA*1088 + sl]),     xqg + o1);
            CPA16((unsigned)__cvta_generic_to_shared(&sm[OFF_XQ + nA*1088 + sl + 4]), xqg + o1 + 4);
            CPA16((unsigned)__cvta_generic_to_shared(&sm[OFF_XK + nA*1088 + sl]),     xkg + o1);
            CPA16((unsigned)__cvta_generic_to_shared(&sm[OFF_XK + nA*1088 + sl + 4]), xkg + o1 + 4);
            CPA16((unsigned)__cvta_generic_to_shared(&sm[OFF_XQ + nB*1088 + sl]),     xqg + o2);
            CPA16((unsigned)__cvta_generic_to_shared(&sm[OFF_XQ + nB*1088 + sl + 4]), xqg + o2 + 4);
            CPA16((unsigned)__cvta_generic_to_shared(&sm[OFF_XK + nB*1088 + sl]),     xkg + o2);
            CPA16((unsigned)__cvta_generic_to_shared(&sm[OFF_XK + nB*1088 + sl + 4]), xkg + o2 + 4);
            CPCOMMIT();
        }
        const float4 cvA0 = *(const float4*)&xvg[(size_t)(2*p)*1024 + tid*8];
        const float4 cvA1 = *(const float4*)&xvg[(size_t)(2*p)*1024 + tid*8 + 4];
        const float4 cvB0 = *(const float4*)&xvg[(size_t)(2*p+1)*1024 + tid*8];
        const float4 cvB1 = *(const float4*)&xvg[(size_t)(2*p+1)*1024 + tid*8 + 4];

        float em, el, em1, el1;
        {
            const float4 e0 = *(const float4*)&sm[OFF_ETA + bA*16 + 0];
            const float4 e1 = *(const float4*)&sm[OFF_ETA + bA*16 + 4];
            const float4 e2 = *(const float4*)&sm[OFF_ETA + bA*16 + 8];
            const float4 e3 = *(const float4*)&sm[OFF_ETA + bA*16 + 12];
            em = ((e0.x+e0.y+e0.z+e0.w) + (e1.x+e1.y+e1.z+e1.w)
                + (e2.x+e2.y+e2.z+e2.w) + (e3.x+e3.y+e3.z+e3.w)) * (1.0f/16.0f);
            el = e3.w;
            const float4 f0v = *(const float4*)&sm[OFF_ETA + bB*16 + 0];
            const float4 f1v = *(const float4*)&sm[OFF_ETA + bB*16 + 4];
            const float4 f2v = *(const float4*)&sm[OFF_ETA + bB*16 + 8];
            const float4 f3v = *(const float4*)&sm[OFF_ETA + bB*16 + 12];
            em1 = ((f0v.x+f0v.y+f0v.z+f0v.w) + (f1v.x+f1v.y+f1v.z+f1v.w)
                 + (f2v.x+f2v.y+f2v.z+f2v.w) + (f3v.x+f3v.y+f3v.z+f3v.w)) * (1.0f/16.0f);
            el1 = f3v.w;
        }

        // ---- one W-pass for BOTH steps; 8 features per thread ----
        float4 z0, z1, zd0, zd1, zn0, zn1, zdn0, zdn1;
        {
            const float4 b0 = *(const float4*)&BB[f0];
            const float4 b1v = *(const float4*)&BB[f0 + 4];
            z0 = b0; z1 = b1v; zd0 = b0; zd1 = b1v;
            zn0 = b0; zn1 = b1v; zdn0 = b0; zdn1 = b1v;
        }
        // A' = xq.xk^T + 1 EVERYWHERE (the +1 folds grad_b1) -> all four init 1
        float a0 = 1.0f, a1 = 1.0f, an0 = 1.0f, an1 = 1.0f, dk = 0.f, dq = 0.f;
        #pragma unroll 2
        for (int j = 0; j < 16; j++) {
            const int d0 = j << 2;
            const float4 xkt = *(const float4*)&xkA_[k*ROWP + d0];
            const float4 xqt = *(const float4*)&xqA [k*ROWP + d0];
            const float4 xkn = *(const float4*)&xkB [k*ROWP + d0];
            const float4 xqn = *(const float4*)&xqB [k*ROWP + d0];
            const float4 xA0 = *(const float4*)&xkA_[q8*ROWP + d0];
            const float4 xA1 = *(const float4*)&xkA_[(q8+8)*ROWP + d0];
            const float4 xB0 = *(const float4*)&xkB [q8*ROWP + d0];
            const float4 xB1 = *(const float4*)&xkB [(q8+8)*ROWP + d0];
            const float4 xF  = *(const float4*)&xkA_[15*ROWP + d0];
            a0  = fmaf(xqt.x, xA0.x, fmaf(xqt.y, xA0.y, fmaf(xqt.z, xA0.z, fmaf(xqt.w, xA0.w, a0))));
            a1  = fmaf(xqt.x, xA1.x, fmaf(xqt.y, xA1.y, fmaf(xqt.z, xA1.z, fmaf(xqt.w, xA1.w, a1))));
            an0 = fmaf(xqn.x, xB0.x, fmaf(xqn.y, xB0.y, fmaf(xqn.z, xB0.z, fmaf(xqn.w, xB0.w, an0))));
            an1 = fmaf(xqn.x, xB1.x, fmaf(xqn.y, xB1.y, fmaf(xqn.z, xB1.z, fmaf(xqn.w, xB1.w, an1))));
            dk  = fmaf(xkn.x, xF.x,  fmaf(xkn.y, xF.y,  fmaf(xkn.z, xF.z,  fmaf(xkn.w, xF.w,  dk))));
            dq  = fmaf(xqn.x, xF.x,  fmaf(xqn.y, xF.y,  fmaf(xqn.z, xF.z,  fmaf(xqn.w, xF.w,  dq))));
            #pragma unroll
            for (int i = 0; i < 4; i++) {
                const float4 w0 = *(const float4*)&W[(d0+i)*64 + f0];
                const float4 w1 = *(const float4*)&W[(d0+i)*64 + f0 + 4];
                const float kt  = (&xkt.x)[i], qt  = (&xqt.x)[i];
                const float kn2 = (&xkn.x)[i], qn2 = (&xqn.x)[i];
                z0.x   = fmaf(kt,  w0.x, z0.x);   z0.y   = fmaf(kt,  w0.y, z0.y);
                z0.z   = fmaf(kt,  w0.z, z0.z);   z0.w   = fmaf(kt,  w0.w, z0.w);
                z1.x   = fmaf(kt,  w1.x, z1.x);   z1.y   = fmaf(kt,  w1.y, z1.y);
                z1.z   = fmaf(kt,  w1.z, z1.z);   z1.w   = fmaf(kt,  w1.w, z1.w);
                zd0.x  = fmaf(qt,  w0.x, zd0.x);  zd0.y  = fmaf(qt,  w0.y, zd0.y);
                zd0.z  = fmaf(qt,  w0.z, zd0.z);  zd0.w  = fmaf(qt,  w0.w, zd0.w);
                zd1.x  = fmaf(qt,  w1.x, zd1.x);  zd1.y  = fmaf(qt,  w1.y, zd1.y);
                zd1.z  = fmaf(qt,  w1.z, zd1.z);  zd1.w  = fmaf(qt,  w1.w, zd1.w);
                zn0.x  = fmaf(kn2, w0.x, zn0.x);  zn0.y  = fmaf(kn2, w0.y, zn0.y);
                zn0.z  = fmaf(kn2, w0.z, zn0.z);  zn0.w  = fmaf(kn2, w0.w, zn0.w);
                zn1.x  = fmaf(kn2, w1.x, zn1.x);  zn1.y  = fmaf(kn2, w1.y, zn1.y);
                zn1.z  = fmaf(kn2, w1.z, zn1.z);  zn1.w  = fmaf(kn2, w1.w, zn1.w);
                zdn0.x = fmaf(qn2, w0.x, zdn0.x); zdn0.y = fmaf(qn2, w0.y, zdn0.y);
                zdn0.z = fmaf(qn2, w0.z, zdn0.z); zdn0.w = fmaf(qn2, w0.w, zdn0.w);
                zdn1.x = fmaf(qn2, w1.x, zdn1.x); zdn1.y = fmaf(qn2, w1.y, zdn1.y);
                zdn1.z = fmaf(qn2, w1.z, zdn1.z); zdn1.w = fmaf(qn2, w1.w, zdn1.w);
            }
        }

        // ---- epilogue step t = 2p ----
        const float4 ck0 = *(const float4*)&xkA_[sl];
        const float4 ck1 = *(const float4*)&xkA_[sl + 4];
        {
            float s1 = (z0.x + z0.y + z0.z + z0.w) + (z1.x + z1.y + z1.z + z1.w);
            float s2 = (z0.x*z0.x + z0.y*z0.y + z0.z*z0.z + z0.w*z0.w)
                     + (z1.x*z1.x + z1.y*z1.y + z1.z*z1.z + z1.w*z1.w);
            #pragma unroll
            for (int m = 4; m >= 1; m >>= 1) {
                s1 += __shfl_xor_sync(~0u, s1, m, 8);
                s2 += __shfl_xor_sync(~0u, s2, m, 8);
            }
            const float mu  = s1 * 0.015625f;
            const float var = fmaf(-mu, mu, s2 * 0.015625f);
            const float r   = rsqrtf(var + 1e-6f);
            float4 gz0, gz1;
            gz0.x = 2.0f * (fmaf(g40.x, (z0.x-mu)*r, be40.x) - cvA0.x + ck0.x);
            gz0.y = 2.0f * (fmaf(g40.y, (z0.y-mu)*r, be40.y) - cvA0.y + ck0.y);
            gz0.z = 2.0f * (fmaf(g40.z, (z0.z-mu)*r, be40.z) - cvA0.z + ck0.z);
            gz0.w = 2.0f * (fmaf(g40.w, (z0.w-mu)*r, be40.w) - cvA0.w + ck0.w);
            gz1.x = 2.0f * (fmaf(g41.x, (z1.x-mu)*r, be41.x) - cvA1.x + ck1.x);
            gz1.y = 2.0f * (fmaf(g41.y, (z1.y-mu)*r, be41.y) - cvA1.y + ck1.y);
            gz1.z = 2.0f * (fmaf(g41.z, (z1.z-mu)*r, be41.z) - cvA1.z + ck1.z);
            gz1.w = 2.0f * (fmaf(g41.w, (z1.w-mu)*r, be41.w) - cvA1.w + ck1.w);
            *(float4*)&GZ[sl]     = gz0;
            *(float4*)&GZ[sl + 4] = gz1;
        }
        __syncthreads();

        const float4 gl0 = *(const float4*)&GZ[15*ROWP + f0];
        const float4 gl1 = *(const float4*)&GZ[15*ROWP + f0 + 4];
        {
            const float fk = -el * (dk + 1.0f);
            const float fq = -el * (dq + 1.0f);
            zn0.x  = fmaf(fk, gl0.x, zn0.x);  zn0.y  = fmaf(fk, gl0.y, zn0.y);
            zn0.z  = fmaf(fk, gl0.z, zn0.z);  zn0.w  = fmaf(fk, gl0.w, zn0.w);
            zn1.x  = fmaf(fk, gl1.x, zn1.x);  zn1.y  = fmaf(fk, gl1.y, zn1.y);
            zn1.z  = fmaf(fk, gl1.z, zn1.z);  zn1.w  = fmaf(fk, gl1.w, zn1.w);
            zdn0.x = fmaf(fq, gl0.x, zdn0.x); zdn0.y = fmaf(fq, gl0.y, zdn0.y);
            zdn0.z = fmaf(fq, gl0.z, zdn0.z); zdn0.w = fmaf(fq, gl0.w, zdn0.w);
            zdn1.x = fmaf(fq, gl1.x, zdn1.x); zdn1.y = fmaf(fq, gl1.y, zdn1.y);
            zdn1.z = fmaf(fq, gl1.z, zdn1.z); zdn1.w = fmaf(fq, gl1.w, zdn1.w);
        }
        {
            float4 c0 = make_float4(0.f,0.f,0.f,0.f), c1 = c0;
            #pragma unroll
            for (int kp = 0; kp < 16; kp++) {
                const float av = (kp < 8) ? __shfl_sync(~0u, a0, kp, 8)
                                          : __shfl_sync(~0u, a1, kp - 8, 8);
                const float4 gv0 = *(const float4*)&GZ[kp*ROWP + f0];
                const float4 gv1 = *(const float4*)&GZ[kp*ROWP + f0 + 4];
                c0.x = fmaf(av, gv0.x, c0.x); c0.y = fmaf(av, gv0.y, c0.y);
                c0.z = fmaf(av, gv0.z, c0.z); c0.w = fmaf(av, gv0.w, c0.w);
                c1.x = fmaf(av, gv1.x, c1.x); c1.y = fmaf(av, gv1.y, c1.y);
                c1.z = fmaf(av, gv1.z, c1.z); c1.w = fmaf(av, gv1.w, c1.w);
            }
            zd0.x = fmaf(-em, c0.x, zd0.x); zd0.y = fmaf(-em, c0.y, zd0.y);
            zd0.z = fmaf(-em, c0.z, zd0.z); zd0.w = fmaf(-em, c0.w, zd0.w);
            zd1.x = fmaf(-em, c1.x, zd1.x); zd1.y = fmaf(-em, c1.y, zd1.y);
            zd1.z = fmaf(-em, c1.z, zd1.z); zd1.w = fmaf(-em, c1.w, zd1.w);
            float t1 = (zd0.x + zd0.y + zd0.z + zd0.w) + (zd1.x + zd1.y + zd1.z + zd1.w);
            float t2 = (zd0.x*zd0.x + zd0.y*zd0.y + zd0.z*zd0.z + zd0.w*zd0.w)
                     + (zd1.x*zd1.x + zd1.y*zd1.y + zd1.z*zd1.z + zd1.w*zd1.w);
            #pragma unroll
            for (int m = 4; m >= 1; m >>= 1) {
                t1 += __shfl_xor_sync(~0u, t1, m, 8);
                t2 += __shfl_xor_sync(~0u, t2, m, 8);
            }
            const float mu2  = t1 * 0.015625f;
            const float var2 = fmaf(-mu2, mu2, t2 * 0.015625f);
            const float r2   = rsqrtf(var2 + 1e-6f);
            const float4 cq0 = *(const float4*)&xqA[sl];
            const float4 cq1 = *(const float4*)&xqA[sl + 4];
            float4 o0, o1;
            o0.x = cq0.x + fmaf(g40.x, (zd0.x-mu2)*r2, be40.x);
            o0.y = cq0.y + fmaf(g40.y, (zd0.y-mu2)*r2, be40.y);
            o0.z = cq0.z + fmaf(g40.z, (zd0.z-mu2)*r2, be40.z);
            o0.w = cq0.w + fmaf(g40.w, (zd0.w-mu2)*r2, be40.w);
            o1.x = cq1.x + fmaf(g41.x, (zd1.x-mu2)*r2, be41.x);
            o1.y = cq1.y + fmaf(g41.y, (zd1.y-mu2)*r2, be41.y);
            o1.z = cq1.z + fmaf(g41.z, (zd1.z-mu2)*r2, be41.z);
            o1.w = cq1.w + fmaf(g41.w, (zd1.w-mu2)*r2, be41.w);
            *(float4*)&og[(size_t)(2*p)*1024 + tid*8]     = o0;
            *(float4*)&og[(size_t)(2*p)*1024 + tid*8 + 4] = o1;
        }
        __syncthreads();

        // ---- epilogue step t+1 ----
        const float4 dkv0 = *(const float4*)&xkB[sl];
        const float4 dkv1 = *(const float4*)&xkB[sl + 4];
        {
            float s1 = (zn0.x + zn0.y + zn0.z + zn0.w) + (zn1.x + zn1.y + zn1.z + zn1.w);
            float s2 = (zn0.x*zn0.x + zn0.y*zn0.y + zn0.z*zn0.z + zn0.w*zn0.w)
                     + (zn1.x*zn1.x + zn1.y*zn1.y + zn1.z*zn1.z + zn1.w*zn1.w);
            #pragma unroll
            for (int m = 4; m >= 1; m >>= 1) {
                s1 += __shfl_xor_sync(~0u, s1, m, 8);
                s2 += __shfl_xor_sync(~0u, s2, m, 8);
            }
            const float mu  = s1 * 0.015625f;
            const float var = fmaf(-mu, mu, s2 * 0.015625f);
            const float r   = rsqrtf(var + 1e-6f);
            float4 gz0, gz1;
            gz0.x = 2.0f * (fmaf(g40.x, (zn0.x-mu)*r, be40.x) - cvB0.x + dkv0.x);
            gz0.y = 2.0f * (fmaf(g40.y, (zn0.y-mu)*r, be40.y) - cvB0.y + dkv0.y);
            gz0.z = 2.0f * (fmaf(g40.z, (zn0.z-mu)*r, be40.z) - cvB0.z + dkv0.z);
            gz0.w = 2.0f * (fmaf(g40.w, (zn0.w-mu)*r, be40.w) - cvB0.w + dkv0.w);
            gz1.x = 2.0f * (fmaf(g41.x, (zn1.x-mu)*r, be41.x) - cvB1.x + dkv1.x);
            gz1.y = 2.0f * (fmaf(g41.y, (zn1.y-mu)*r, be41.y) - cvB1.y + dkv1.y);
            gz1.z = 2.0f * (fmaf(g41.z, (zn1.z-mu)*r, be41.z) - cvB1.z + dkv1.z);
            gz1.w = 2.0f * (fmaf(g41.w, (zn1.w-mu)*r, be41.w) - cvB1.w + dkv1.w);
            *(float4*)&GZ[sl]     = gz0;
            *(float4*)&GZ[sl + 4] = gz1;
        }
        __syncthreads();
        {
            float4 c0 = make_float4(0.f,0.f,0.f,0.f), c1 = c0;
            #pragma unroll
            for (int kp = 0; kp < 16; kp++) {
                const float av = (kp < 8) ? __shfl_sync(~0u, an0, kp, 8)
                                          : __shfl_sync(~0u, an1, kp - 8, 8);
                const float4 gv0 = *(const float4*)&GZ[kp*ROWP + f0];
                const float4 gv1 = *(const float4*)&GZ[kp*ROWP + f0 + 4];
                c0.x = fmaf(av, gv0.x, c0.x); c0.y = fmaf(av, gv0.y, c0.y);
                c0.z = fmaf(av, gv0.z, c0.z); c0.w = fmaf(av, gv0.w, c0.w);
                c1.x = fmaf(av, gv1.x, c1.x); c1.y = fmaf(av, gv1.y, c1.y);
                c1.z = fmaf(av, gv1.z, c1.z); c1.w = fmaf(av, gv1.w, c1.w);
            }
            zdn0.x = fmaf(-em1, c0.x, zdn0.x); zdn0.y = fmaf(-em1, c0.y, zdn0.y);
            zdn0.z = fmaf(-em1, c0.z, zdn0.z); zdn0.w = fmaf(-em1, c0.w, zdn0.w);
            zdn1.x = fmaf(-em1, c1.x, zdn1.x); zdn1.y = fmaf(-em1, c1.y, zdn1.y);
            zdn1.z = fmaf(-em1, c1.z, zdn1.z); zdn1.w = fmaf(-em1, c1.w, zdn1.w);
            float t1 = (zdn0.x + zdn0.y + zdn0.z + zdn0.w) + (zdn1.x + zdn1.y + zdn1.z + zdn1.w);
            float t2 = (zdn0.x*zdn0.x + zdn0.y*zdn0.y + zdn0.z*zdn0.z + zdn0.w*zdn0.w)
                     + (zdn1.x*zdn1.x + zdn1.y*zdn1.y + zdn1.z*zdn1.z + zdn1.w*zdn1.w);
            #pragma unroll
            for (int m = 4; m >= 1; m >>= 1) {
                t1 += __shfl_xor_sync(~0u, t1, m, 8);
                t2 += __shfl_xor_sync(~0u, t2, m, 8);
            }
            const float mu2  = t1 * 0.015625f;
            const float var2 = fmaf(-mu2, mu2, t2 * 0.015625f);
            const float r2   = rsqrtf(var2 + 1e-6f);
            const float4 cq0 = *(const float4*)&xqB[sl];
            const float4 cq1 = *(const float4*)&xqB[sl + 4];
            float4 o0, o1;
            o0.x = cq0.x + fmaf(g40.x, (zdn0.x-mu2)*r2, be40.x);
            o0.y = cq0.y + fmaf(g40.y, (zdn0.y-mu2)*r2, be40.y);
            o0.z = cq0.z + fmaf(g40.z, (zdn0.z-mu2)*r2, be40.z);
            o0.w = cq0.w + fmaf(g40.w, (zdn0.w-mu2)*r2, be40.w);
            o1.x = cq1.x + fmaf(g41.x, (zdn1.x-mu2)*r2, be41.x);
            o1.y = cq1.y + fmaf(g41.y, (zdn1.y-mu2)*r2, be41.y);
            o1.z = cq1.z + fmaf(g41.z, (zdn1.z-mu2)*r2, be41.z);
            o1.w = cq1.w + fmaf(g41.w, (zdn1.w-mu2)*r2, be41.w);
            *(float4*)&og[(size_t)(2*p+1)*1024 + tid*8]     = o0;
            *(float4*)&og[(size_t)(2*p+1)*1024 + tid*8 + 4] = o1;
        }

        if (p + 1 < NPAIR) {
            const float4 ga0 = *(const float4*)&GZ[15*ROWP + f0];
            const float4 ga1 = *(const float4*)&GZ[15*ROWP + f0 + 4];
            #pragma unroll
            for (int jj = 0; jj < 4; jj++) {
                const int d = k + 16*jj;
                const float cf  = -el  * xkA_[15*ROWP + d];
                const float cf1 = -el1 * xkB [15*ROWP + d];
                float4 w0 = *(float4*)&W[d*64 + f0];
                float4 w1 = *(float4*)&W[d*64 + f0 + 4];
                w0.x = fmaf(cf, gl0.x, fmaf(cf1, ga0.x, w0.x));
                w0.y = fmaf(cf, gl0.y, fmaf(cf1, ga0.y, w0.y));
                w0.z = fmaf(cf, gl0.z, fmaf(cf1, ga0.z, w0.z));
                w0.w = fmaf(cf, gl0.w, fmaf(cf1, ga0.w, w0.w));
                w1.x = fmaf(cf, gl1.x, fmaf(cf1, ga1.x, w1.x));
                w1.y = fmaf(cf, gl1.y, fmaf(cf1, ga1.y, w1.y));
                w1.z = fmaf(cf, gl1.z, fmaf(cf1, ga1.z, w1.z));
                w1.w = fmaf(cf, gl1.w, fmaf(cf1, ga1.w, w1.w));
                *(float4*)&W[d*64 + f0]     = w0;
                *(float4*)&W[d*64 + f0 + 4] = w1;
            }
            if (tid < 8) {   // k==0, f0 == tid*8
                float4 b0 = *(float4*)&BB[f0];
                float4 b1v = *(float4*)&BB[f0 + 4];
                b0.x = fmaf(-el, gl0.x, fmaf(-el1, ga0.x, b0.x));
                b0.y = fmaf(-el, gl0.y, fmaf(-el1, ga0.y, b0.y));
                b0.z = fmaf(-el, gl0.z, fmaf(-el1, ga0.z, b0.z));
                b0.w = fmaf(-el, gl0.w, fmaf(-el1, ga0.w, b0.w));
                b1v.x = fmaf(-el, gl1.x, fmaf(-el1, ga1.x, b1v.x));
                b1v.y = fmaf(-el, gl1.y, fmaf(-el1, ga1.y, b1v.y));
                b1v.z = fmaf(-el, gl1.z, fmaf(-el1, ga1.z, b1v.z));
                b1v.w = fmaf(-el, gl1.w, fmaf(-el1, ga1.w, b1v.w));
                *(float4*)&BB[f0]     = b0;
                *(float4*)&BB[f0 + 4] = b1v;
            }
            CPWAIT0();
            #pragma unroll
            for (int s = 0; s < 2; s++) {
                const int nb = (s == 0) ? nA : nB;
                const float4 tk0 = *(const float4*)&sm[OFF_XK + nb*1088 + sl];
                const float4 tk1 = *(const float4*)&sm[OFF_XK + nb*1088 + sl + 4];
                float ss = tk0.x*tk0.x + tk0.y*tk0.y + tk0.z*tk0.z + tk0.w*tk0.w
                         + tk1.x*tk1.x + tk1.y*tk1.y + tk1.z*tk1.z + tk1.w*tk1.w;
                #pragma unroll
                for (int m = 4; m >= 1; m >>= 1) ss += __shfl_xor_sync(~0u, ss, m, 8);
                if (q8 == 0) sm[OFF_ETA + nb*16 + k] = 0.01f / (1.0f + fmaxf(sqrtf(ss), 1e-6f));
            }
            __syncthreads();
        }
    }
}

// ============================ fused kernel ==================================
__global__ __launch_bounds__(128, 4)
void fused_kernel(const float* __restrict__ XQ, const float* __restrict__ XK,
                  const float* __restrict__ XV, const float* __restrict__ W1,
                  const float* __restrict__ b1, const float* __restrict__ gam,
                  const float* __restrict__ bet, float* __restrict__ out)
{
    extern __shared__ float sm[];
    const int bid = blockIdx.x;

    if (bid < NBH) {
        scan_role(sm, bid, XK, XV, W1, b1, gam, bet);
        return;
    }
    const int cid = bid - NBH;
    const int c   = cid >> 6;      // chunk-major: early waves need early chunks
    const int bh  = cid & 63;
    chunk_role(sm, c, bh, XQ, XK, XV, gam, bet, out);
}

extern "C" void kernel_launch(void* const* d_in, const int* in_sizes, int n_in,
                              void* d_out, int out_size) {
    const float* XQ  = (const float*)d_in[0];
    const float* XK  = (const float*)d_in[1];
    const float* XV  = (const float*)d_in[2];
    const float* W1  = (const float*)d_in[3];
    const float* b1  = (const float*)d_in[4];
    const float* gam = (const float*)d_in[5];
    const float* bet = (const float*)d_in[6];
    float* out = (float*)d_out;

    const int smem = SMF * (int)sizeof(float);       // ~56 KB
    static int configured = 0;
    if (!configured) {
        cudaFuncSetAttribute(fused_kernel, cudaFuncAttributeMaxDynamicSharedMemorySize, smem);
        configured = 1;
    }
    reset_kernel<<<1, 64>>>();
    fused_kernel<<<NBH + NBH * NCHUNK, 128, smem>>>(XQ, XK, XV, W1, b1, gam, bet, out);
}

// round 17
// speedup vs baseline: 1.0753x; 1.0753x over previous
#include <cuda_runtime.h>

#define TT     512
#define CHUNK  16
#define NPAIR  8
#define NCHUNK 32
#define NBH    64
#define ROWP   68

__device__ float g_Wsnap[(size_t)NBH * NCHUNK * 4096];
__device__ float g_bsnap[(size_t)NBH * NCHUNK * 64];
__device__ int   g_prog[NBH];

#define CPA16(saddr, gptr) \
    asm volatile("cp.async.cg.shared.global [%0], [%1], 16;" :: "r"(saddr), "l"(gptr))
#define CPCOMMIT() asm volatile("cp.async.commit_group;")
#define CPWAIT0()  asm volatile("cp.async.wait_group 0;")

// chunk-role dyn smem layout (floats)
#define OFF_XQ  4096                  // 4 buffers x 1088
#define OFF_XK  (OFF_XQ + 4352)
#define OFF_GZ  (OFF_XK + 4352)
#define OFF_BB  (OFF_GZ + 1088)
#define OFF_ETA (OFF_BB + 64)         // 4 x 16
#define SMF     (OFF_ETA + 64)        // 14016 floats = 56 KB

__global__ void reset_kernel() {
    if (threadIdx.x < NBH) g_prog[threadIdx.x] = 0;
}

// ====== scan role: redundant-LN scan, 2 barriers/step, 128 threads ==========
// Every warp holds 16 W rows in registers AND redundantly computes the full
// combine->LN->gz chain (inputs are all replicated/shared), so no gz
// broadcast barrier and no update barrier are needed.
__device__ __forceinline__
void scan_role(float* sm, int bh,
               const float* __restrict__ XK, const float* __restrict__ XV,
               const float* __restrict__ W1, const float* __restrict__ b1,
               const float* __restrict__ gam, const float* __restrict__ bet)
{
    float* const xs = sm;            // [2][64] parity-buffered xk15
    float* const pz = sm + 128;      // [4][64] matvec partials

    const int tid  = threadIdx.x;    // < 128
    const int lane = tid & 31;
    const int w    = tid >> 5;       // 0..3
    const int h    = bh & 15;

    float Wa[16], Wb[16];
    {
        const float* Wg = W1 + (size_t)h * 4096;
        #pragma unroll
        for (int i = 0; i < 16; i++) {
            const int d = w*16 + i;
            Wa[i] = Wg[d*64 + lane];
            Wb[i] = Wg[d*64 + lane + 32];
        }
    }
    float bav = b1[h*64 + lane], bbv = b1[h*64 + lane + 32];
    const float ga  = gam[h*64 + lane], gb  = gam[h*64 + lane + 32];
    const float bea = bet[h*64 + lane], beb = bet[h*64 + lane + 32];

    const size_t base = (size_t)bh * (TT * 1024) + 960;   // row 15 of each step
    const float* xkg = XK + base;
    const float* xvg = XV + base;

    if (tid < 64) xs[tid] = xkg[tid];
    float va = xvg[lane], vb = xvg[lane + 32];   // every warp loads (redundant)
    __syncthreads();

    int par = 0;
    for (int t = 0; t < TT; t++) {
        // snapshot W,b at chunk boundary (state = updates <= t-1)
        if ((t & (CHUNK-1)) == 0) {
            float* ws = g_Wsnap + ((size_t)bh * NCHUNK + (t >> 4)) * 4096;
            #pragma unroll
            for (int i = 0; i < 16; i++) {
                const int d = w*16 + i;
                ws[d*64 + lane]      = Wa[i];
                ws[d*64 + lane + 32] = Wb[i];
            }
            if (w == 0) {
                float* bs = g_bsnap + ((size_t)bh * NCHUNK + (t >> 4)) * 64;
                bs[lane] = bav; bs[lane + 32] = bbv;
            }
        }

        // prefetch next step's row-15 (xk by tid<64, xv redundantly per warp)
        float kn = 0.f, nva = 0.f, nvb = 0.f;
        if (t + 1 < TT) {
            const size_t o = (size_t)(t+1) * 1024;
            if (tid < 64) kn = xkg[o + tid];
            nva = xvg[o + lane]; nvb = xvg[o + lane + 32];
        }

        // partial matvec over this warp's 16 rows of xs[par] (2 chains)
        float x16[16];
        float za0 = 0.f, za1 = 0.f, zb0 = 0.f, zb1 = 0.f;
        #pragma unroll
        for (int i = 0; i < 8; i++) {
            x16[i]   = xs[par*64 + w*16 + i];
            x16[i+8] = xs[par*64 + w*16 + i + 8];
            za0 = fmaf(x16[i],   Wa[i],   za0);
            za1 = fmaf(x16[i+8], Wa[i+8], za1);
            zb0 = fmaf(x16[i],   Wb[i],   zb0);
            zb1 = fmaf(x16[i+8], Wb[i+8], zb1);
        }
        pz[w*64 + lane]      = za0 + za1;
        pz[w*64 + lane + 32] = zb0 + zb1;
        // stage next xs (dead slot; last reader passed the previous barrier)
        if (tid < 64) xs[(par^1)*64 + tid] = kn;
        __syncthreads();                                    // B1: pz + xs ready

        // publish snapshot flag (all warps' STGs issued before B1)
        if ((t & (CHUNK-1)) == 0 && tid == 0) {
            __threadfence();
            atomicExch(&g_prog[bh], (t >> 4) + 1);
        }

        // ---- redundant combine + LN + gz in EVERY warp ----
        const float xa = xs[par*64 + lane], xb = xs[par*64 + lane + 32];
        float za = bav + ((pz[lane] + pz[64+lane]) + (pz[128+lane] + pz[192+lane]));
        float zb = bbv + ((pz[lane+32] + pz[64+lane+32]) + (pz[128+lane+32] + pz[192+lane+32]));
        float s1 = za + zb;
        float s2 = za*za + zb*zb;
        float ss = xa*xa + xb*xb;
        #pragma unroll
        for (int m = 16; m >= 1; m >>= 1) {
            s1 += __shfl_xor_sync(~0u, s1, m);
            s2 += __shfl_xor_sync(~0u, s2, m);
            ss += __shfl_xor_sync(~0u, ss, m);
        }
        const float el  = 0.01f / (1.0f + fmaxf(sqrtf(ss), 1e-6f));
        const float mu  = s1 * 0.015625f;
        const float var = fmaf(-mu, mu, s2 * 0.015625f);
        const float r   = rsqrtf(var + 1e-6f);
        const float gza = 2.0f * (fmaf(ga, (za-mu)*r, bea) - va + xa);
        const float gzb = 2.0f * (fmaf(gb, (zb-mu)*r, beb) - vb + xb);
        bav = fmaf(-el, gza, bav);            // replicated b update
        bbv = fmaf(-el, gzb, bbv);
        const float ea = el * gza, eb = el * gzb;
        #pragma unroll
        for (int i = 0; i < 16; i++) {        // local W rank-1 update
            Wa[i] = fmaf(-ea, x16[i], Wa[i]);
            Wb[i] = fmaf(-eb, x16[i], Wb[i]);
        }
        __syncthreads();                                    // B2: pz/xs reuse safe

        va = nva; vb = nvb; par ^= 1;
    }
    if (tid == 0) { __threadfence(); atomicExch(&g_prog[bh], NCHUNK + 1); }
}

// ====== chunk role: parallel chunk replay, paired steps (R13-proven) ========
__device__ __forceinline__
void chunk_role(float* sm, int c, int bh,
                const float* __restrict__ XQ, const float* __restrict__ XK,
                const float* __restrict__ XV, const float* __restrict__ gam,
                const float* __restrict__ bet, float* __restrict__ out)
{
    float* const W  = sm;
    float* const GZ = sm + OFF_GZ;
    float* const BB = sm + OFF_BB;

    const int tid = threadIdx.x;
    const int h   = bh & 15;
    const int k   = tid >> 4;
    const int q   = tid & 15;
    const int f0  = q << 2;
    const int sl  = k*ROWP + f0;

    if (tid == 0) {
        volatile int* f = &g_prog[bh];
        while (*f < c + 1) __nanosleep(256);
    }
    __syncthreads();
    __threadfence();

    const size_t base = (size_t)bh * (TT * 1024) + (size_t)c * (CHUNK * 1024);
    const float* xqg = XQ + base;
    const float* xkg = XK + base;
    const float* xvg = XV + base;
    float*       og  = out + base;

    {
        const float* Ws = g_Wsnap + ((size_t)bh * NCHUNK + c) * 4096;
        #pragma unroll
        for (int i = 0; i < 4; i++)
            *(float4*)&W[i*1024 + tid*4] = *(const float4*)&Ws[i*1024 + tid*4];
        if (tid < 16) {
            const float* bs = g_bsnap + ((size_t)bh * NCHUNK + c) * 64;
            *(float4*)&BB[tid*4] = *(const float4*)&bs[tid*4];
        }
    }
    const float4 g4  = *(const float4*)&gam[h*64 + f0];
    const float4 be4 = *(const float4*)&bet[h*64 + f0];

    #pragma unroll
    for (int s = 0; s < 2; s++) {
        const float4 tq = *(const float4*)&xqg[s*1024 + tid*4];
        const float4 tk = *(const float4*)&xkg[s*1024 + tid*4];
        *(float4*)&sm[OFF_XQ + s*1088 + sl] = tq;
        *(float4*)&sm[OFF_XK + s*1088 + sl] = tk;
        float ss = tk.x*tk.x + tk.y*tk.y + tk.z*tk.z + tk.w*tk.w;
        #pragma unroll
        for (int m = 8; m >= 1; m >>= 1) ss += __shfl_xor_sync(~0u, ss, m, 16);
        if (q == 0) sm[OFF_ETA + s*16 + k] = 0.01f / (1.0f + fmaxf(sqrtf(ss), 1e-6f));
    }
    __syncthreads();

    for (int p = 0; p < NPAIR; p++) {
        const int bA = (p & 1) * 2, bB = bA + 1;
        const int nA = ((p + 1) & 1) * 2, nB = nA + 1;
        const float* xqA  = sm + OFF_XQ + bA*1088;
        const float* xkA_ = sm + OFF_XK + bA*1088;
        const float* xqB  = sm + OFF_XQ + bB*1088;
        const float* xkB  = sm + OFF_XK + bB*1088;

        if (p + 1 < NPAIR) {
            const size_t o1 = (size_t)(2*p+2)*1024 + tid*4;
            const size_t o2 = o1 + 1024;
            CPA16((unsigned)__cvta_generic_to_shared(&sm[OFF_XQ + nA*1088 + sl]), xqg + o1);
            CPA16((unsigned)__cvta_generic_to_shared(&sm[OFF_XK + nA*1088 + sl]), xkg + o1);
            CPA16((unsigned)__cvta_generic_to_shared(&sm[OFF_XQ + nB*1088 + sl]), xqg + o2);
            CPA16((unsigned)__cvta_generic_to_shared(&sm[OFF_XK + nB*1088 + sl]), xkg + o2);
            CPCOMMIT();
        }
        const float4 cv  = *(const float4*)&xvg[(size_t)(2*p)*1024 + tid*4];
        const float4 cv1 = *(const float4*)&xvg[(size_t)(2*p+1)*1024 + tid*4];

        float em, el, em1, el1;
        {
            const float4 e0 = *(const float4*)&sm[OFF_ETA + bA*16 + 0];
            const float4 e1 = *(const float4*)&sm[OFF_ETA + bA*16 + 4];
            const float4 e2 = *(const float4*)&sm[OFF_ETA + bA*16 + 8];
            const float4 e3 = *(const float4*)&sm[OFF_ETA + bA*16 + 12];
            em = ((e0.x+e0.y+e0.z+e0.w) + (e1.x+e1.y+e1.z+e1.w)
                + (e2.x+e2.y+e2.z+e2.w) + (e3.x+e3.y+e3.z+e3.w)) * (1.0f/16.0f);
            el = e3.w;
            const float4 f0v = *(const float4*)&sm[OFF_ETA + bB*16 + 0];
            const float4 f1v = *(const float4*)&sm[OFF_ETA + bB*16 + 4];
            const float4 f2v = *(const float4*)&sm[OFF_ETA + bB*16 + 8];
            const float4 f3v = *(const float4*)&sm[OFF_ETA + bB*16 + 12];
            em1 = ((f0v.x+f0v.y+f0v.z+f0v.w) + (f1v.x+f1v.y+f1v.z+f1v.w)
                 + (f2v.x+f2v.y+f2v.z+f2v.w) + (f3v.x+f3v.y+f3v.z+f3v.w)) * (1.0f/16.0f);
            el1 = f3v.w;
        }

        float4 z, zd, zn, zdn;
        {
            const float4 b4 = *(const float4*)&BB[f0];
            z = b4; zd = b4; zn = b4; zdn = b4;
        }
        float a = 1.0f, an = 1.0f, dk = 0.f, dq = 0.f;
        #pragma unroll 4
        for (int j = 0; j < 16; j++) {
            const int d0 = j << 2;
            const float4 xkt = *(const float4*)&xkA_[k*ROWP + d0];
            const float4 xqt = *(const float4*)&xqA [k*ROWP + d0];
            const float4 xkn = *(const float4*)&xkB [k*ROWP + d0];
            const float4 xqn = *(const float4*)&xqB [k*ROWP + d0];
            const float4 xAt = *(const float4*)&xkA_[q*ROWP + d0];
            const float4 xAn = *(const float4*)&xkB [q*ROWP + d0];
            const float4 xF  = *(const float4*)&xkA_[15*ROWP + d0];
            a  = fmaf(xqt.x, xAt.x, fmaf(xqt.y, xAt.y, fmaf(xqt.z, xAt.z, fmaf(xqt.w, xAt.w, a))));
            an = fmaf(xqn.x, xAn.x, fmaf(xqn.y, xAn.y, fmaf(xqn.z, xAn.z, fmaf(xqn.w, xAn.w, an))));
            dk = fmaf(xkn.x, xF.x, fmaf(xkn.y, xF.y, fmaf(xkn.z, xF.z, fmaf(xkn.w, xF.w, dk))));
            dq = fmaf(xqn.x, xF.x, fmaf(xqn.y, xF.y, fmaf(xqn.z, xF.z, fmaf(xqn.w, xF.w, dq))));
            #pragma unroll
            for (int i = 0; i < 4; i++) {
                const float4 w4 = *(const float4*)&W[(d0+i)*64 + f0];
                const float kt  = (&xkt.x)[i], qt  = (&xqt.x)[i];
                const float kn2 = (&xkn.x)[i], qn2 = (&xqn.x)[i];
                z.x   = fmaf(kt,  w4.x, z.x);   z.y   = fmaf(kt,  w4.y, z.y);
                z.z   = fmaf(kt,  w4.z, z.z);   z.w   = fmaf(kt,  w4.w, z.w);
                zd.x  = fmaf(qt,  w4.x, zd.x);  zd.y  = fmaf(qt,  w4.y, zd.y);
                zd.z  = fmaf(qt,  w4.z, zd.z);  zd.w  = fmaf(qt,  w4.w, zd.w);
                zn.x  = fmaf(kn2, w4.x, zn.x);  zn.y  = fmaf(kn2, w4.y, zn.y);
                zn.z  = fmaf(kn2, w4.z, zn.z);  zn.w  = fmaf(kn2, w4.w, zn.w);
                zdn.x = fmaf(qn2, w4.x, zdn.x); zdn.y = fmaf(qn2, w4.y, zdn.y);
                zdn.z = fmaf(qn2, w4.z, zdn.z); zdn.w = fmaf(qn2, w4.w, zdn.w);
            }
        }

        // epilogue step t = 2p
        const float4 ck = *(const float4*)&xkA_[sl];
        {
            float s1 = z.x + z.y + z.z + z.w;
            float s2 = z.x*z.x + z.y*z.y + z.z*z.z + z.w*z.w;
            #pragma unroll
            for (int m = 8; m >= 1; m >>= 1) {
                s1 += __shfl_xor_sync(~0u, s1, m, 16);
                s2 += __shfl_xor_sync(~0u, s2, m, 16);
            }
            const float mu  = s1 * 0.015625f;
            const float var = fmaf(-mu, mu, s2 * 0.015625f);
            const float r   = rsqrtf(var + 1e-6f);
            float4 gz;
            gz.x = 2.0f * (fmaf(g4.x, (z.x-mu)*r, be4.x) - cv.x + ck.x);
            gz.y = 2.0f * (fmaf(g4.y, (z.y-mu)*r, be4.y) - cv.y + ck.y);
            gz.z = 2.0f * (fmaf(g4.z, (z.z-mu)*r, be4.z) - cv.z + ck.z);
            gz.w = 2.0f * (fmaf(g4.w, (z.w-mu)*r, be4.w) - cv.w + ck.w);
            *(float4*)&GZ[sl] = gz;
        }
        __syncthreads();

        const float4 gl = *(const float4*)&GZ[15*ROWP + f0];
        {
            const float fk  = -el * (dk + 1.0f);
            const float fq2 = -el * (dq + 1.0f);
            zn.x  = fmaf(fk,  gl.x, zn.x);  zn.y  = fmaf(fk,  gl.y, zn.y);
            zn.z  = fmaf(fk,  gl.z, zn.z);  zn.w  = fmaf(fk,  gl.w, zn.w);
            zdn.x = fmaf(fq2, gl.x, zdn.x); zdn.y = fmaf(fq2, gl.y, zdn.y);
            zdn.z = fmaf(fq2, gl.z, zdn.z); zdn.w = fmaf(fq2, gl.w, zdn.w);
        }
        {
            float4 cc = make_float4(0.f,0.f,0.f,0.f);
            #pragma unroll
            for (int kp = 0; kp < 16; kp++) {
                const float av  = __shfl_sync(~0u, a, kp, 16);
                const float4 gv = *(const float4*)&GZ[kp*ROWP + f0];
                cc.x = fmaf(av, gv.x, cc.x); cc.y = fmaf(av, gv.y, cc.y);
                cc.z = fmaf(av, gv.z, cc.z); cc.w = fmaf(av, gv.w, cc.w);
            }
            zd.x = fmaf(-em, cc.x, zd.x); zd.y = fmaf(-em, cc.y, zd.y);
            zd.z = fmaf(-em, cc.z, zd.z); zd.w = fmaf(-em, cc.w, zd.w);
            float t1 = zd.x + zd.y + zd.z + zd.w;
            float t2 = zd.x*zd.x + zd.y*zd.y + zd.z*zd.z + zd.w*zd.w;
            #pragma unroll
            for (int m = 8; m >= 1; m >>= 1) {
                t1 += __shfl_xor_sync(~0u, t1, m, 16);
                t2 += __shfl_xor_sync(~0u, t2, m, 16);
            }
            const float mu2  = t1 * 0.015625f;
            const float var2 = fmaf(-mu2, mu2, t2 * 0.015625f);
            const float r2   = rsqrtf(var2 + 1e-6f);
            const float4 cq = *(const float4*)&xqA[sl];
            float4 o;
            o.x = cq.x + fmaf(g4.x, (zd.x-mu2)*r2, be4.x);
            o.y = cq.y + fmaf(g4.y, (zd.y-mu2)*r2, be4.y);
            o.z = cq.z + fmaf(g4.z, (zd.z-mu2)*r2, be4.z);
            o.w = cq.w + fmaf(g4.w, (zd.w-mu2)*r2, be4.w);
            *(float4*)&og[(size_t)(2*p)*1024 + tid*4] = o;
        }
        __syncthreads();

        // epilogue step t+1
        const float4 ck1 = *(const float4*)&xkB[sl];
        {
            float s1 = zn.x + zn.y + zn.z + zn.w;
            float s2 = zn.x*zn.x + zn.y*zn.y + zn.z*zn.z + zn.w*zn.w;
            #pragma unroll
            for (int m = 8; m >= 1; m >>= 1) {
                s1 += __shfl_xor_sync(~0u, s1, m, 16);
                s2 += __shfl_xor_sync(~0u, s2, m, 16);
            }
            const float mu  = s1 * 0.015625f;
            const float var = fmaf(-mu, mu, s2 * 0.015625f);
            const float r   = rsqrtf(var + 1e-6f);
            float4 gz;
            gz.x = 2.0f * (fmaf(g4.x, (zn.x-mu)*r, be4.x) - cv1.x + ck1.x);
            gz.y = 2.0f * (fmaf(g4.y, (zn.y-mu)*r, be4.y) - cv1.y + ck1.y);
            gz.z = 2.0f * (fmaf(g4.z, (zn.z-mu)*r, be4.z) - cv1.z + ck1.z);
            gz.w = 2.0f * (fmaf(g4.w, (zn.w-mu)*r, be4.w) - cv1.w + ck1.w);
            *(float4*)&GZ[sl] = gz;
        }
        __syncthreads();
        {
            float4 cc = make_float4(0.f,0.f,0.f,0.f);
            #pragma unroll
            for (int kp = 0; kp < 16; kp++) {
                const float av  = __shfl_sync(~0u, an, kp, 16);
                const float4 gv = *(const float4*)&GZ[kp*ROWP + f0];
                cc.x = fmaf(av, gv.x, cc.x); cc.y = fmaf(av, gv.y, cc.y);
                cc.z = fmaf(av, gv.z, cc.z); cc.w = fmaf(av, gv.w, cc.w);
            }
            zdn.x = fmaf(-em1, cc.x, zdn.x); zdn.y = fmaf(-em1, cc.y, zdn.y);
            zdn.z = fmaf(-em1, cc.z, zdn.z); zdn.w = fmaf(-em1, cc.w, zdn.w);
            float t1 = zdn.x + zdn.y + zdn.z + zdn.w;
            float t2 = zdn.x*zdn.x + zdn.y*zdn.y + zdn.z*zdn.z + zdn.w*zdn.w;
            #pragma unroll
            for (int m = 8; m >= 1; m >>= 1) {
                t1 += __shfl_xor_sync(~0u, t1, m, 16);
                t2 += __shfl_xor_sync(~0u, t2, m, 16);
            }
            const float mu2  = t1 * 0.015625f;
            const float var2 = fmaf(-mu2, mu2, t2 * 0.015625f);
            const float r2   = rsqrtf(var2 + 1e-6f);
            const float4 cq1 = *(const float4*)&xqB[sl];
            float4 o;
            o.x = cq1.x + fmaf(g4.x, (zdn.x-mu2)*r2, be4.x);
            o.y = cq1.y + fmaf(g4.y, (zdn.y-mu2)*r2, be4.y);
            o.z = cq1.z + fmaf(g4.z, (zdn.z-mu2)*r2, be4.z);
            o.w = cq1.w + fmaf(g4.w, (zdn.w-mu2)*r2, be4.w);
            *(float4*)&og[(size_t)(2*p+1)*1024 + tid*4] = o;
        }

        if (p + 1 < NPAIR) {
            const float4 gl1 = *(const float4*)&GZ[15*ROWP + f0];
            #pragma unroll
            for (int jj = 0; jj < 4; jj++) {
                const int d = k + 16*jj;
                const float cf  = -el  * xkA_[15*ROWP + d];
                const float cf1 = -el1 * xkB [15*ROWP + d];
                float4 w4 = *(float4*)&W[d*64 + f0];
                w4.x = fmaf(cf, gl.x, fmaf(cf1, gl1.x, w4.x));
                w4.y = fmaf(cf, gl.y, fmaf(cf1, gl1.y, w4.y));
                w4.z = fmaf(cf, gl.z, fmaf(cf1, gl1.z, w4.z));
                w4.w = fmaf(cf, gl.w, fmaf(cf1, gl1.w, w4.w));
                *(float4*)&W[d*64 + f0] = w4;
            }
            if (tid < 16) {
                float4 bv = *(float4*)&BB[f0];
                bv.x = fmaf(-el, gl.x, fmaf(-el1, gl1.x, bv.x));
                bv.y = fmaf(-el, gl.y, fmaf(-el1, gl1.y, bv.y));
                bv.z = fmaf(-el, gl.z, fmaf(-el1, gl1.z, bv.z));
                bv.w = fmaf(-el, gl.w, fmaf(-el1, gl1.w, bv.w));
                *(float4*)&BB[f0] = bv;
            }
            CPWAIT0();
            #pragma unroll
            for (int s = 0; s < 2; s++) {
                const int nb = (s == 0) ? nA : nB;
                const float4 tk = *(const float4*)&sm[OFF_XK + nb*1088 + sl];
                float ss = tk.x*tk.x + tk.y*tk.y + tk.z*tk.z + tk.w*tk.w;
                #pragma unroll
                for (int m = 8; m >= 1; m >>= 1) ss += __shfl_xor_sync(~0u, ss, m, 16);
                if (q == 0) sm[OFF_ETA + nb*16 + k] = 0.01f / (1.0f + fmaxf(sqrtf(ss), 1e-6f));
            }
            __syncthreads();
        }
    }
}

// ============================ fused kernel ==================================
__global__ __launch_bounds__(256, 3)
void fused_kernel(const float* __restrict__ XQ, const float* __restrict__ XK,
                  const float* __restrict__ XV, const float* __restrict__ W1,
                  const float* __restrict__ b1, const float* __restrict__ gam,
                  const float* __restrict__ bet, float* __restrict__ out)
{
    extern __shared__ float sm[];
    const int bid = blockIdx.x;

    if (bid < NBH) {
        if (threadIdx.x >= 128) return;     // scan role uses 4 warps
        scan_role(sm, bid, XK, XV, W1, b1, gam, bet);
        return;
    }
    const int cid = bid - NBH;
    const int c   = cid >> 6;      // chunk-major: early waves need early chunks
    const int bh  = cid & 63;
    chunk_role(sm, c, bh, XQ, XK, XV, gam, bet, out);
}

extern "C" void kernel_launch(void* const* d_in, const int* in_sizes, int n_in,
                              void* d_out, int out_size) {
    const float* XQ  = (const float*)d_in[0];
    const float* XK  = (const float*)d_in[1];
    const float* XV  = (const float*)d_in[2];
    const float* W1  = (const float*)d_in[3];
    const float* b1  = (const float*)d_in[4];
    const float* gam = (const float*)d_in[5];
    const float* bet = (const float*)d_in[6];
    float* out = (float*)d_out;

    const int smem = SMF * (int)sizeof(float);       // ~56 KB
    static int configured = 0;
    if (!configured) {
        cudaFuncSetAttribute(fused_kernel, cudaFuncAttributeMaxDynamicSharedMemorySize, smem);
        configured = 1;
    }
    reset_kernel<<<1, 64>>>();
    fused_kernel<<<NBH + NBH * NCHUNK, 256, smem>>>(XQ, XK, XV, W1, b1, gam, bet, out);
}